// round 16
// baseline (speedup 1.0000x reference)
#include <cuda_runtime.h>
#include <cstdint>

// Problem constants
#define NB     16
#define NA     1024
#define PP     65536             // pairs per batch
#define NPAIR  (NB * PP)         // 1,048,576
#define NWAVE  8
#define TOT    (NB * NA)         // 16384 atoms
#define NBLK   32                // placement blocks per batch
#define CAP    128               // bucket capacity (max count ~99)
#define GRID   512               // one persistent wave: 4/SM x 148 = 592 >= 512
#define CUTOFF 6.0f
#define PI_F   3.14159265358979f
#define LOG2E  1.4426950408889634f

// Scratch (device globals; every data buffer is fully rewritten each replay;
// barrier state is self-resetting: ctr returns to 0, flag is sense-free)
__device__ int g_blkcnt[NB * NBLK * NA];                        // 2 MB
__device__ int g_count [TOT];
__device__ unsigned int g_packed[NPAIR];                        // (i0<<8)|localpos
__device__ __align__(16) float4 g_payload[(size_t)TOT * CAP];   // 32 MB
__device__ volatile int g_bar_ctr;    // zero-init; last arriver resets to 0
__device__ volatile int g_bar_flag;   // sense-reversal flag (value irrelevant)

// Software grid barrier.  Safe because all GRID blocks are co-resident
// (launch_bounds(256,4): regs<=64, smem 16KB -> 4 blocks/SM, 592 slots).
// Epoch is read BEFORE arrival, so late readers still see the pre-flip value.
__device__ __forceinline__ void grid_barrier() {
    __syncthreads();
    __threadfence();                      // all threads: publish prior STGs
    if (threadIdx.x == 0) {
        int epoch = g_bar_flag;
        if (atomicAdd((int*)&g_bar_ctr, 1) == GRID - 1) {
            g_bar_ctr = 0;                // self-reset for next barrier/replay
            __threadfence();
            g_bar_flag = epoch ^ 1;       // release
        } else {
            while (g_bar_flag == epoch) { }
        }
        __threadfence();
    }
    __syncthreads();
}

// ---- f32x2 packed helpers (PTX-only; ptxas won't auto-fuse FFMA2) --------
typedef unsigned long long u64;
#define PACK2(out, lo, hi) \
    asm("mov.b64 %0, {%1, %2};" : "=l"(out) : "f"(lo), "f"(hi))
#define UNPACK2(lo, hi, in) \
    asm("mov.b64 {%0, %1}, %2;" : "=f"(lo), "=f"(hi) : "l"(in))
#define FMA2(d, a, b, c) \
    asm("fma.rn.f32x2 %0, %1, %2, %3;" : "=l"(d) : "l"(a), "l"(b), "l"(c))
#define MUL2(d, a, b) \
    asm("mul.rn.f32x2 %0, %1, %2;" : "=l"(d) : "l"(a), "l"(b))
#define ADD2(d, a, b) \
    asm("add.rn.f32x2 %0, %1, %2;" : "=l"(d) : "l"(a), "l"(b))
#define EX2(d, a) \
    asm("ex2.approx.ftz.f32 %0, %1;" : "=f"(d) : "f"(a))

// k2 inner body: dual-wave f32x2 accumulation of the 10 unique moments.
// ia0n/ia1n are pre-scaled by -log2e so exp(-ia t^2) = ex2(ia_n * t^2).
__device__ __forceinline__ void body(
    float4 v, float rs0, float rs1, float ia0n, float ia1n, u64* acc)
{
    float ux = v.x, uy = v.y, uz = v.z, dist = v.w;
    float xc   = fminf(dist * (1.f / CUTOFF), 1.f);
    float fcut = 0.5f * (__cosf(PI_F * xc) + 1.f);

    float t0 = dist - rs0, t1 = dist - rs1;
    float e0, e1;
    EX2(e0, ia0n * t0 * t0);
    EX2(e1, ia1n * t1 * t1);
    float fr0 = fcut * e0, fr1 = fcut * e1;

    u64 fr, X, Y, Z;
    PACK2(fr, fr0, fr1);
    PACK2(X, ux, ux); PACK2(Y, uy, uy); PACK2(Z, uz, uz);

    u64 m[6];
    MUL2(m[0], X, X); MUL2(m[1], X, Y); MUL2(m[2], X, Z);
    MUL2(m[3], Y, Y); MUL2(m[4], Y, Z); MUL2(m[5], Z, Z);

    ADD2(acc[0], acc[0], fr);            // level 0
    FMA2(acc[1], X, fr, acc[1]);         // level 1
    FMA2(acc[2], Y, fr, acc[2]);
    FMA2(acc[3], Z, fr, acc[3]);
#pragma unroll
    for (int k = 0; k < 6; k++)          // level 2 (unique moments)
        FMA2(acc[4 + k], m[k], fr, acc[4 + k]);
}

// ---------------------------------------------------------------------------
// Fused persistent kernel: hist -> barrier -> scan+place -> barrier -> compute
// All phases use the same 512x256 shape (each phase's natural grid).
// ---------------------------------------------------------------------------
__global__ void __launch_bounds__(256, 4) k_fused(
    const int*   __restrict__ atom_index,
    const float* __restrict__ shifts,
    const float* __restrict__ coords,
    const int*   __restrict__ species,
    const float* __restrict__ rs,
    const float* __restrict__ inta,
    const float* __restrict__ params,
    float*       __restrict__ out)
{
    __shared__ union {
        int hist[NA];                        // phase 1 (4 KB)
        struct { float sc[NA * 3]; int soffs[NA]; } p;   // phase 2 (16 KB)
    } sm;

    int b     = blockIdx.x >> 5;             // 32 blocks per batch
    int bi    = blockIdx.x & 31;
    int pbase = bi * 2048 + threadIdx.x;

    // ===== Phase 1: per-block smem histogram (zero global atomics) =====
    {
        const int* ai0 = atom_index + (size_t)b * 2 * PP;
        for (int i = threadIdx.x; i < NA; i += 256) sm.hist[i] = 0;
        __syncthreads();

        int i0[8];
#pragma unroll
        for (int k = 0; k < 8; k++) i0[k] = ai0[pbase + k * 256];

        int lp[8];
#pragma unroll
        for (int k = 0; k < 8; k++) lp[k] = atomicAdd(&sm.hist[i0[k]], 1);

#pragma unroll
        for (int k = 0; k < 8; k++) {
            g_packed[(size_t)b * PP + pbase + k * 256] =
                ((unsigned int)i0[k] << 8) |
                (unsigned int)(lp[k] < 255 ? lp[k] : 255);
        }

        __syncthreads();
        int* dst = g_blkcnt + ((size_t)blockIdx.x << 10);
        for (int i = threadIdx.x; i < NA; i += 256) dst[i] = sm.hist[i];
    }

    grid_barrier();

    // ===== Phase 2: inline prefix scan + placement (no atomics) =====
    {
        const int* base = g_blkcnt + ((size_t)b << 15);   // b * 32 * 1024
        int off[4] = {0, 0, 0, 0};
        for (int j = 0; j < bi; j++) {
            const int* row = base + (j << 10);
#pragma unroll
            for (int q = 0; q < 4; q++) off[q] += row[threadIdx.x + q * 256];
        }
#pragma unroll
        for (int q = 0; q < 4; q++) sm.p.soffs[threadIdx.x + q * 256] = off[q];
        if (bi == 31) {
            const int* row = base + (31 << 10);
#pragma unroll
            for (int q = 0; q < 4; q++)
                g_count[(b << 10) + threadIdx.x + q * 256] =
                    off[q] + row[threadIdx.x + q * 256];
        }

        const float* cb = coords + (size_t)b * NA * 3;
        for (int i = threadIdx.x; i < NA * 3; i += 256) sm.p.sc[i] = cb[i];

        const int* ai1 = atom_index + (size_t)b * 2 * PP + PP;
        unsigned int pk[8];
        int i1[8];
#pragma unroll
        for (int k = 0; k < 8; k++) {
            pk[k] = g_packed[(size_t)b * PP + pbase + k * 256];
            i1[k] = ai1[pbase + k * 256];
        }
        __syncthreads();

        const float* shb = shifts + (size_t)b * PP * 3;
#pragma unroll
        for (int k = 0; k < 8; k++) {
            int p   = pbase + k * 256;
            int i0  = (int)(pk[k] >> 8);
            int pos = sm.p.soffs[i0] + (int)(pk[k] & 0xFF);

            float sx = shb[(size_t)p * 3 + 0];
            float sy = shb[(size_t)p * 3 + 1];
            float sz = shb[(size_t)p * 3 + 2];

            float dx = sm.p.sc[i0 * 3 + 0] - sm.p.sc[i1[k] * 3 + 0] + sx;
            float dy = sm.p.sc[i0 * 3 + 1] - sm.p.sc[i1[k] * 3 + 1] + sy;
            float dz = sm.p.sc[i0 * 3 + 2] - sm.p.sc[i1[k] * 3 + 2] + sz;
            // Invalid shifts (<= -1e9) give huge dist -> fcut=0 and ex2
            // underflow downstream, matching the reference's where(valid,...,0).
            float dist = sqrtf(dx * dx + dy * dy + dz * dz);
            float inv  = (dist > 1e-12f) ? (1.f / dist) : 1.f;
            if (pos < CAP) {
                g_payload[(size_t)(b * NA + i0) * CAP + pos] =
                    make_float4(dx * inv, dy * inv, dz * inv, dist);
            }
        }
    }

    grid_barrier();

    // ===== Phase 3: per-atom gather + finalize (R12 k2, tile=blockIdx) =====
    {
        int tid = blockIdx.x * 256 + threadIdx.x;   // TOT*8 threads
        int n   = tid >> 3;                         // atom
        int w0  = (tid & 3) * 2;                    // wave pair
        int h   = (tid >> 2) & 1;                   // list half

        int spec = species[n];
        float rs0  = rs[spec * NWAVE + w0];
        float rs1  = rs[spec * NWAVE + w0 + 1];
        float ia0n = -inta[spec * NWAVE + w0]     * LOG2E;
        float ia1n = -inta[spec * NWAVE + w0 + 1] * LOG2E;

        int cnt = g_count[n];
        if (cnt > CAP) cnt = CAP;

        u64 acc[10];
#pragma unroll
        for (int k = 0; k < 10; k++) acc[k] = 0ULL;   // {0.f, 0.f}

        const float4* pl = g_payload + (size_t)n * CAP;

        // strided loop j = h, h+2, ... with prefetch depth 2 (clamped reads)
        float4 v0 = pl[h];
        float4 v1 = pl[(h + 2) & (CAP - 1)];

        int j = h;
        for (; j + 2 < cnt; j += 4) {
            float4 n0 = pl[(j + 4) & (CAP - 1)];
            float4 n1 = pl[(j + 6) & (CAP - 1)];
            body(v0, rs0, rs1, ia0n, ia1n, acc);
            body(v1, rs0, rs1, ia0n, ia1n, acc);
            v0 = n0; v1 = n1;
        }
        if (j < cnt) body(v0, rs0, rs1, ia0n, ia1n, acc);

        // combine the 2 list-halves (partner lane differs in bit 2)
#pragma unroll
        for (int k = 0; k < 10; k++) {
            u64 other = __shfl_xor_sync(0xFFFFFFFF, acc[k], 4);
            ADD2(acc[k], acc[k], other);
        }

        if (h == 0) {
            float pm = params[spec];
            float a0[10], a1[10];
#pragma unroll
            for (int k = 0; k < 10; k++) UNPACK2(a0[k], a1[k], acc[k]);

            float s00 = a0[0] * a0[0];
            float s01 = a1[0] * a1[0];
            float s10 = a0[1]*a0[1] + a0[2]*a0[2] + a0[3]*a0[3];
            float s11 = a1[1]*a1[1] + a1[2]*a1[2] + a1[3]*a1[3];
            // diag + 2x off-diag (xy,xz,yz appear twice in the reference's 9)
            float s20 = a0[4]*a0[4] + a0[7]*a0[7] + a0[9]*a0[9]
                      + 2.f * (a0[5]*a0[5] + a0[6]*a0[6] + a0[8]*a0[8]);
            float s21 = a1[4]*a1[4] + a1[7]*a1[7] + a1[9]*a1[9]
                      + 2.f * (a1[5]*a1[5] + a1[6]*a1[6] + a1[8]*a1[8]);

            float* o = out + (size_t)n * 24;
            o[0  + w0] = pm * s00;  o[0  + w0 + 1] = pm * s01;
            o[8  + w0] = pm * s10;  o[8  + w0 + 1] = pm * s11;
            o[16 + w0] = pm * s20;  o[16 + w0 + 1] = pm * s21;
        }
    }
}

// ---------------------------------------------------------------------------
// Launch
// ---------------------------------------------------------------------------
extern "C" void kernel_launch(void* const* d_in, const int* in_sizes, int n_in,
                              void* d_out, int out_size) {
    const float* coords     = (const float*)d_in[0];
    // d_in[1] = numatoms (unused)
    const int*   atom_index = (const int*)  d_in[2];
    const float* shifts     = (const float*)d_in[3];
    const int*   species    = (const int*)  d_in[4];
    const float* rs         = (const float*)d_in[5];
    const float* inta       = (const float*)d_in[6];
    const float* params     = (const float*)d_in[7];
    float* out = (float*)d_out;

    k_fused<<<GRID, 256>>>(atom_index, shifts, coords,
                           species, rs, inta, params, out);
}